// round 13
// baseline (speedup 1.0000x reference)
#include <cuda_runtime.h>

#define CC 128
#define HH 16
#define WW 16
#define BB 32
#define VV 8192
#define NELEM (BB*CC*HH*WW)   // 1048576 elements (== VV*CC — the remap trap!)
#define SN 5

// ---------------- device scratch (no allocations allowed) ----------------
__device__ float g_rest[NELEM];
__device__ float g_fhat[NELEM];
__device__ float g_x[VV*CC];        // pooled vectors, [n][c], n-major
__device__ float g_esq[VV];
__device__ float g_pd[32768];       // partial min dist per (n, chunk)
__device__ int   g_pi[32768];
__device__ int   g_idx[VV];
__device__ float g_h[NELEM];        // current-scale h (upsampled, pre-phi)
__device__ float g_loss[SN*256];    // per-scale per-conv-block loss partials

// ---------------- init ----------------
__global__ void init_kernel(const float* __restrict__ f){
  int i = blockIdx.x*blockDim.x + threadIdx.x;
  if (i < NELEM){ g_rest[i]=f[i]; g_fhat[i]=0.f; }
}

__global__ void esq_kernel(const float* __restrict__ emb){
  int v = blockIdx.x*blockDim.x + threadIdx.x;
  if (v >= VV) return;
  const float4* r = (const float4*)(emb + (size_t)v*CC);
  float s=0.f;
  #pragma unroll
  for (int q=0;q<CC/4;q++){ float4 e=r[q]; s += e.x*e.x+e.y*e.y+e.z*e.z+e.w*e.w; }
  g_esq[v]=s;
}

// ---------------- avg pool (area interpolate) ----------------
__global__ void pool_kernel(int pn, int N){
  int t = blockIdx.x*blockDim.x + threadIdx.x;
  if (t >= N*CC) return;
  int c = t & (CC-1); int n = t >> 7;
  int pp = pn*pn; int b = n/pp; int r = n - b*pp; int y = r/pn; int x = r - y*pn;
  int s = HH/pn;
  const float* base = g_rest + ((b*CC + c)*HH + y*s)*WW + x*s;
  float sum = 0.f;
  for (int dy=0; dy<s; dy++)
    for (int dx=0; dx<s; dx++)
      sum += base[dy*WW + dx];
  g_x[(size_t)n*CC + c] = sum * (1.f/(float)(s*s));
}

// ---------------- argmin over codebook: stage A (tiled distance GEMM) ----------------
// d = e_sq[v] - 2*dot(x,e)  (|x|^2 dropped: row-constant, argmin-invariant — proven
// equivalent to the full formula by the R12 on-device A/B, flag==0)
__global__ void __launch_bounds__(128) argmin_stageA(const float* __restrict__ emb, int nch){
  __shared__ float xs[128][32];   // k-major x tile
  __shared__ float es[128][64];   // k-major e tile
  int tid = threadIdx.x;
  int n0 = blockIdx.x * 32;
  int L = VV / nch;
  int vbeg = blockIdx.y * L;

  for (int idx = tid; idx < 32*128; idx += 128){
    int i = idx & 31, k = idx >> 5;
    xs[k][i] = g_x[(size_t)(n0+i)*CC + k];
  }

  float bd[4]; int bi[4];
  #pragma unroll
  for (int i=0;i<4;i++){ bd[i]=3.4e38f; bi[i]=0; }
  int tn = tid & 7, tv = tid >> 3;   // 8 n-groups x 16 v-groups
  int nb = tn*4, vb = tv*4;

  for (int sub=0; sub<L; sub+=64){
    int v0 = vbeg + sub;
    __syncthreads();
    {
      int vr = tid >> 1, half = (tid & 1)*64;
      const float4* src = (const float4*)(emb + (size_t)(v0+vr)*CC + half);
      #pragma unroll
      for (int q=0;q<16;q++){
        float4 e4 = src[q];
        int k = half + q*4;
        es[k  ][vr]=e4.x; es[k+1][vr]=e4.y; es[k+2][vr]=e4.z; es[k+3][vr]=e4.w;
      }
    }
    __syncthreads();

    float acc[4][4];
    #pragma unroll
    for (int i=0;i<4;i++)
      #pragma unroll
      for (int j=0;j<4;j++) acc[i][j]=0.f;

    #pragma unroll 4
    for (int k=0;k<128;k++){
      float4 ev = *(const float4*)&es[k][vb];
      float4 xv = *(const float4*)&xs[k][nb];
      float xa[4] = {xv.x,xv.y,xv.z,xv.w};
      float ea[4] = {ev.x,ev.y,ev.z,ev.w};
      #pragma unroll
      for (int i=0;i<4;i++)
        #pragma unroll
        for (int j=0;j<4;j++)
          acc[i][j] += xa[i]*ea[j];
    }

    float eq[4];
    #pragma unroll
    for (int j=0;j<4;j++) eq[j] = g_esq[v0 + vb + j];
    #pragma unroll
    for (int i=0;i<4;i++)
      #pragma unroll
      for (int j=0;j<4;j++){
        float d = eq[j] - 2.f*acc[i][j];
        if (d < bd[i]) { bd[i]=d; bi[i]=v0+vb+j; }   // ascending v + strict< => first-min
      }
  }

  __syncthreads();
  float* rd = &es[0][0];           // 512 floats (rows 0..7)
  int*   ri = (int*)&es[8][0];     // 512 ints   (rows 8..15)
  #pragma unroll
  for (int i=0;i<4;i++){
    rd[(nb+i)*16 + tv] = bd[i];
    ri[(nb+i)*16 + tv] = bi[i];
  }
  __syncthreads();
  if (tid < 32){
    float best = 3.4e38f; int besti = 0x7fffffff;
    for (int t=0;t<16;t++){
      float d = rd[tid*16 + t]; int ii = ri[tid*16 + t];
      if (d < best || (d == best && ii < besti)){ best = d; besti = ii; }
    }
    g_pd[(size_t)(n0+tid)*nch + blockIdx.y] = best;
    g_pi[(size_t)(n0+tid)*nch + blockIdx.y] = besti;
  }
}

__global__ void argmin_stageB(int N, int nch){
  int n = blockIdx.x*blockDim.x + threadIdx.x;
  if (n >= N) return;
  float bd = g_pd[(size_t)n*nch]; int bi = g_pi[(size_t)n*nch];
  for (int c=1;c<nch;c++){
    float d = g_pd[(size_t)n*nch + c]; int ii = g_pi[(size_t)n*nch + c];
    if (d < bd || (d == bd && ii < bi)){ bd = d; bi = ii; }
  }
  g_idx[n] = bi;
}

// ---------------- bicubic upsample (jax cubic: Keys a=-0.5 + tap-sum norm) ----
__device__ __forceinline__ float keysf(float x){
  x = fabsf(x);
  if (x < 1.f) return ((1.5f*x - 2.5f)*x)*x + 1.f;
  if (x < 2.f) return ((-0.5f*x + 2.5f)*x - 4.f)*x + 2.f;
  return 0.f;
}
__device__ __forceinline__ void mkw(int i, int pn, float* w){
  float sf = (i + 0.5f)*((float)pn*(1.f/16.f)) - 0.5f;
  float s = 0.f;
  for (int k=0;k<pn;k++){ float wv = keysf(sf - (float)k); w[k]=wv; s+=wv; }
  float inv = 1.f/s;
  for (int k=0;k<pn;k++) w[k]*=inv;
}

__global__ void upsample_kernel(const float* __restrict__ emb, int pn){
  int t = blockIdx.x*blockDim.x + threadIdx.x;
  if (t >= NELEM) return;
  int c = t & 127; int r = t >> 7;
  int x = r & 15; int y = (r>>4)&15; int b = r>>8;
  float wy[8], wx[8];
  mkw(y, pn, wy); mkw(x, pn, wx);
  const int* idxp = g_idx + b*pn*pn;
  float val = 0.f;
  for (int ky=0; ky<pn; ky++){
    float wyv = wy[ky];
    for (int kx=0; kx<pn; kx++){
      float ww = wyv*wx[kx];
      if (ww != 0.f)
        val += ww * emb[(size_t)idxp[ky*pn+kx]*CC + c];
    }
  }
  g_h[((b*CC+c)*HH+y)*WW+x] = val;
}

__global__ void gather_kernel(const float* __restrict__ emb){
  int t = blockIdx.x*blockDim.x + threadIdx.x;
  if (t >= NELEM) return;
  int c = t & 127; int r = t >> 7;
  int x = r & 15; int y = (r>>4)&15; int b = r>>8;
  g_h[((b*CC+c)*HH+y)*WW+x] = emb[(size_t)g_idx[(b*16+y)*16+x]*CC + c];
}

// ---------------- Phi conv3x3 + blend + residual update + loss partial ----------------
__global__ void __launch_bounds__(128) conv_phi_kernel(
    const float* __restrict__ f,
    const float* __restrict__ w,
    const float* __restrict__ bias,
    int si){
  __shared__ float in_s[8*18*18];
  __shared__ float w_s[8][9][16];
  __shared__ float red[128];
  int tid = threadIdx.x;
  int b = blockIdx.y, cog = blockIdx.x;
  int tx = tid & 15, ty = tid >> 4;

  float acc0[16], acc1[16];
  #pragma unroll
  for (int i=0;i<16;i++){acc0[i]=0.f;acc1[i]=0.f;}

  for (int cb=0; cb<16; cb++){
    __syncthreads();
    for (int idx=tid; idx<8*324; idx+=128){
      int q = idx/324; int r2 = idx - q*324;
      int iy = r2/18 - 1; int ix = r2 - (r2/18)*18 - 1;
      int ci = cb*8 + q;
      float v = 0.f;
      if (iy>=0 && iy<16 && ix>=0 && ix<16)
        v = g_h[((b*CC+ci)*HH+iy)*WW+ix];
      in_s[idx] = v;
    }
    for (int idx=tid; idx<1152; idx+=128){
      int q = idx/144; int r2 = idx - q*144;
      int t9 = r2 >> 4; int co = r2 & 15;
      w_s[q][t9][co] = w[((size_t)(cog*16+co)*CC + cb*8+q)*9 + t9];
    }
    __syncthreads();

    #pragma unroll
    for (int q=0;q<8;q++){
      float a[9], c2[9];
      const float* base = in_s + q*324;
      #pragma unroll
      for (int dy=0;dy<3;dy++)
        #pragma unroll
        for (int dx=0;dx<3;dx++){
          a[dy*3+dx]  = base[(ty+dy)*18 + tx+dx];
          c2[dy*3+dx] = base[(ty+8+dy)*18 + tx+dx];
        }
      #pragma unroll
      for (int t9=0;t9<9;t9++){
        float av = a[t9], bv = c2[t9];
        #pragma unroll
        for (int co=0; co<16; co++){
          float wv = w_s[q][t9][co];
          acc0[co] += wv*av;
          acc1[co] += wv*bv;
        }
      }
    }
  }

  float lsum = 0.f;
  #pragma unroll
  for (int co16=0; co16<16; co16++){
    int co = cog*16 + co16;
    float bs = bias[co];
    {
      int off = ((b*CC+co)*HH + ty)*WW + tx;
      float out = 0.5f*g_h[off] + 0.5f*(acc0[co16] + bs);
      float fh = g_fhat[off] + out;
      g_fhat[off] = fh;
      g_rest[off] = g_rest[off] - out;
      float d = fh - f[off];
      lsum += d*d;
    }
    {
      int off = ((b*CC+co)*HH + ty+8)*WW + tx;
      float out = 0.5f*g_h[off] + 0.5f*(acc1[co16] + bs);
      float fh = g_fhat[off] + out;
      g_fhat[off] = fh;
      g_rest[off] = g_rest[off] - out;
      float d = fh - f[off];
      lsum += d*d;
    }
  }
  red[tid] = lsum;
  __syncthreads();
  for (int s=64; s>0; s>>=1){
    if (tid < s) red[tid] += red[tid+s];
    __syncthreads();
  }
  if (tid==0) g_loss[si*256 + b*8 + cog] = red[0];
}

// ---------------- output + loss (R0 layout: f_hat at [0..N), loss at [N]) ----------------
__global__ void output_kernel(const float* __restrict__ f, float* __restrict__ out, int out_size){
  int i = blockIdx.x*blockDim.x + threadIdx.x;
  if (out_size >= NELEM && i < NELEM)
    out[i] = (g_fhat[i] - f[i]) + f[i];   // straight-through rounding replicated
}

__global__ void loss_kernel(float* __restrict__ out, int out_size){
  __shared__ float m[SN];
  int tid = threadIdx.x;
  if (tid < SN){
    float s = 0.f;
    for (int i=0;i<256;i++) s += g_loss[tid*256+i];
    m[tid] = s * (1.f/(float)NELEM);
  }
  __syncthreads();
  if (tid == 0){
    float loss = 0.f;
    for (int si=0; si<SN; si++) loss += 0.25f*m[si] + m[si];
    loss *= (1.f/(float)SN);
    int pos = -1;
    if (out_size > NELEM) pos = NELEM;
    else if (out_size == 1) pos = 0;
    if (pos >= 0) out[pos] = loss;
  }
}

// ---------------- launch ----------------
extern "C" void kernel_launch(void* const* d_in, const int* in_sizes, int n_in,
                              void* d_out, int out_size){
  // NO size-based remap: NELEM == VV*CC (1,048,576) made the old remap alias
  // f to the embedding table — the bug that poisoned rounds 4-10.
  const float* f   = (const float*)d_in[0];
  const float* emb = (const float*)d_in[1];
  const float* pw  = (const float*)d_in[2];
  const float* pb  = (const float*)d_in[3];
  float* out = (float*)d_out;

  init_kernel<<<NELEM/256, 256>>>(f);
  esq_kernel<<<VV/256, 256>>>(emb);

  const int pns[SN]  = {1,2,4,8,16};
  const int chs[SN]  = {64,32,16,8,4};
  // kphi[2]=2 per exact IEEE-754 walk of np.linspace(1/12, 11/12, 4):
  //   t2 - 0.5 = 5/36 - (8/9)*2^-54  <  0.5 - t1 = 5/36 + ~2*2^-54  => argmin = 2.
  // First clean test of this value (R4's apparent falsification was remap-poisoned).
  const int kphi[SN] = {0,1,2,2,3};

  for (int si=0; si<SN; si++){
    int pn = pns[si];
    int N = BB*pn*pn;
    pool_kernel<<<(N*CC+255)/256, 256>>>(pn, N);
    dim3 ga(N/32, chs[si]);
    argmin_stageA<<<ga, 128>>>(emb, chs[si]);
    argmin_stageB<<<(N+255)/256, 256>>>(N, chs[si]);
    if (si < SN-1) upsample_kernel<<<NELEM/256, 256>>>(emb, pn);
    else           gather_kernel<<<NELEM/256, 256>>>(emb);
    conv_phi_kernel<<<dim3(8,32), 128>>>(f, pw + (size_t)kphi[si]*CC*CC*9, pb + kphi[si]*CC, si);
  }

  output_kernel<<<NELEM/256, 256>>>(f, out, out_size);
  loss_kernel<<<1, 32>>>(out, out_size);
}

// round 15
// speedup vs baseline: 1.0439x; 1.0439x over previous
#include <cuda_runtime.h>

#define CC 128
#define HH 16
#define WW 16
#define BB 32
#define VV 8192
#define NELEM (BB*CC*HH*WW)   // 1048576 elements (== VV*CC — never size-remap!)
#define SN 5

typedef unsigned long long ull;

__device__ __forceinline__ ull pack2(float lo, float hi){
  ull r; asm("mov.b64 %0, {%1, %2};" : "=l"(r) : "f"(lo), "f"(hi)); return r;
}
__device__ __forceinline__ void unpack2(ull v, float& lo, float& hi){
  asm("mov.b64 {%0, %1}, %2;" : "=f"(lo), "=f"(hi) : "l"(v));
}
// packed dual fp32 FMA (Blackwell FFMA2; lanes independent => bit-exact per-lane fp32)
__device__ __forceinline__ ull fma2(ull a, ull b, ull c){
  ull r; asm("fma.rn.f32x2 %0, %1, %2, %3;" : "=l"(r) : "l"(a), "l"(b), "l"(c)); return r;
}

// ---------------- device scratch (no allocations allowed) ----------------
__device__ float g_rest[NELEM];
__device__ float g_fhat[NELEM];
__device__ float g_x[VV*CC];        // pooled vectors, [n][c], n-major
__device__ float g_esq[VV];
__device__ float g_pd[32768];       // partial min dist per (n, chunk)
__device__ int   g_pi[32768];
__device__ int   g_idx[VV];
__device__ float g_h[NELEM];        // current-scale h (upsampled, pre-phi)
__device__ float g_loss[SN*256];    // per-scale per-conv-block loss partials

// ---------------- init ----------------
__global__ void init_kernel(const float* __restrict__ f){
  int i = blockIdx.x*blockDim.x + threadIdx.x;
  if (i < NELEM){ g_rest[i]=f[i]; g_fhat[i]=0.f; }
}

__global__ void esq_kernel(const float* __restrict__ emb){
  int v = blockIdx.x*blockDim.x + threadIdx.x;
  if (v >= VV) return;
  const float4* r = (const float4*)(emb + (size_t)v*CC);
  float s=0.f;
  #pragma unroll
  for (int q=0;q<CC/4;q++){ float4 e=r[q]; s += e.x*e.x+e.y*e.y+e.z*e.z+e.w*e.w; }
  g_esq[v]=s;
}

// ---------------- avg pool (area interpolate) ----------------
__global__ void pool_kernel(int pn, int N){
  int t = blockIdx.x*blockDim.x + threadIdx.x;
  if (t >= N*CC) return;
  int c = t & (CC-1); int n = t >> 7;
  int pp = pn*pn; int b = n/pp; int r = n - b*pp; int y = r/pn; int x = r - y*pn;
  int s = HH/pn;
  const float* base = g_rest + ((b*CC + c)*HH + y*s)*WW + x*s;
  float sum = 0.f;
  for (int dy=0; dy<s; dy++)
    for (int dx=0; dx<s; dx++)
      sum += base[dy*WW + dx];
  g_x[(size_t)n*CC + c] = sum * (1.f/(float)(s*s));
}

// ---------------- argmin stage A: tiled distance GEMM with f32x2 packed FMA ----------------
// block = 32 n × 64 v sub-tile, 128 threads = 16 n-groups (2n) × 8 v-groups (8v).
// d = e_sq[v] - 2*dot(x,e): per-(n,v) accumulation chain identical (k ascending,
// single fma chain) to the R13-passing kernel — bit-exact distances.
__global__ void __launch_bounds__(128) argmin_stageA(const float* __restrict__ emb, int nch){
  __shared__ __align__(16) float xs[128][32];   // k-major x tile (16KB)
  __shared__ __align__(16) float es[128][64];   // k-major e tile (32KB)
  int tid = threadIdx.x;
  int n0 = blockIdx.x * 32;
  int L = VV / nch;
  int vbeg = blockIdx.y * L;

  for (int idx = tid; idx < 32*128; idx += 128){
    int i = idx & 31, k = idx >> 5;
    xs[k][i] = g_x[(size_t)(n0+i)*CC + k];
  }

  float bd[2]; int bi[2];
  bd[0]=3.4e38f; bd[1]=3.4e38f; bi[0]=0; bi[1]=0;
  int tn = tid & 15, tv = tid >> 4;   // 16 n-groups x 8 v-groups
  int nb = tn*2, vb = tv*8;

  for (int sub=0; sub<L; sub+=64){
    int v0 = vbeg + sub;
    __syncthreads();
    {
      int vr = tid >> 1, half = (tid & 1)*64;
      const float4* src = (const float4*)(emb + (size_t)(v0+vr)*CC + half);
      #pragma unroll
      for (int q=0;q<16;q++){
        float4 e4 = src[q];
        int k = half + q*4;
        es[k  ][vr]=e4.x; es[k+1][vr]=e4.y; es[k+2][vr]=e4.z; es[k+3][vr]=e4.w;
      }
    }
    __syncthreads();

    ull acc[2][4];
    #pragma unroll
    for (int i=0;i<2;i++)
      #pragma unroll
      for (int j=0;j<4;j++) acc[i][j]=0ull;   // two packed 0.0f

    #pragma unroll 4
    for (int k=0;k<128;k++){
      float2 xv = *(const float2*)&xs[k][nb];
      ull x0 = pack2(xv.x, xv.x);
      ull x1 = pack2(xv.y, xv.y);
      const ulonglong2* ep = (const ulonglong2*)&es[k][vb];
      ulonglong2 ea = ep[0];
      ulonglong2 eb = ep[1];
      acc[0][0] = fma2(x0, ea.x, acc[0][0]);
      acc[0][1] = fma2(x0, ea.y, acc[0][1]);
      acc[0][2] = fma2(x0, eb.x, acc[0][2]);
      acc[0][3] = fma2(x0, eb.y, acc[0][3]);
      acc[1][0] = fma2(x1, ea.x, acc[1][0]);
      acc[1][1] = fma2(x1, ea.y, acc[1][1]);
      acc[1][2] = fma2(x1, eb.x, acc[1][2]);
      acc[1][3] = fma2(x1, eb.y, acc[1][3]);
    }

    // epilogue: v ascending per n, strict < => first-min (same semantics as R13)
    #pragma unroll
    for (int j2=0;j2<4;j2++){
      int v = v0 + vb + j2*2;
      float eqlo = g_esq[v], eqhi = g_esq[v+1];
      #pragma unroll
      for (int i=0;i<2;i++){
        float alo, ahi; unpack2(acc[i][j2], alo, ahi);
        float dlo = eqlo - 2.f*alo;
        if (dlo < bd[i]){ bd[i]=dlo; bi[i]=v; }
        float dhi = eqhi - 2.f*ahi;
        if (dhi < bd[i]){ bd[i]=dhi; bi[i]=v+1; }
      }
    }
  }

  // block reduce (reuse es as scratch): per n, 8 v-group candidates
  __syncthreads();
  float* rd = &es[0][0];           // 256 floats (rows 0..3)
  int*   ri = (int*)&es[8][0];     // 256 ints   (rows 8..11)
  #pragma unroll
  for (int i=0;i<2;i++){
    rd[(nb+i)*8 + tv] = bd[i];
    ri[(nb+i)*8 + tv] = bi[i];
  }
  __syncthreads();
  if (tid < 32){
    float best = 3.4e38f; int besti = 0x7fffffff;
    #pragma unroll
    for (int t=0;t<8;t++){
      float d = rd[tid*8 + t]; int ii = ri[tid*8 + t];
      if (d < best || (d == best && ii < besti)){ best = d; besti = ii; }
    }
    g_pd[(size_t)(n0+tid)*nch + blockIdx.y] = best;
    g_pi[(size_t)(n0+tid)*nch + blockIdx.y] = besti;
  }
}

__global__ void argmin_stageB(int N, int nch){
  int n = blockIdx.x*blockDim.x + threadIdx.x;
  if (n >= N) return;
  float bd = g_pd[(size_t)n*nch]; int bi = g_pi[(size_t)n*nch];
  for (int c=1;c<nch;c++){
    float d = g_pd[(size_t)n*nch + c]; int ii = g_pi[(size_t)n*nch + c];
    if (d < bd || (d == bd && ii < bi)){ bd = d; bi = ii; }
  }
  g_idx[n] = bi;
}

// ---------------- bicubic upsample (jax cubic: Keys a=-0.5 + tap-sum norm) ----
__device__ __forceinline__ float keysf(float x){
  x = fabsf(x);
  if (x < 1.f) return ((1.5f*x - 2.5f)*x)*x + 1.f;
  if (x < 2.f) return ((-0.5f*x + 2.5f)*x - 4.f)*x + 2.f;
  return 0.f;
}
__device__ __forceinline__ void mkw(int i, int pn, float* w){
  float sf = (i + 0.5f)*((float)pn*(1.f/16.f)) - 0.5f;
  float s = 0.f;
  for (int k=0;k<pn;k++){ float wv = keysf(sf - (float)k); w[k]=wv; s+=wv; }
  float inv = 1.f/s;
  for (int k=0;k<pn;k++) w[k]*=inv;
}

__global__ void upsample_kernel(const float* __restrict__ emb, int pn){
  int t = blockIdx.x*blockDim.x + threadIdx.x;
  if (t >= NELEM) return;
  int c = t & 127; int r = t >> 7;
  int x = r & 15; int y = (r>>4)&15; int b = r>>8;
  float wy[8], wx[8];
  mkw(y, pn, wy); mkw(x, pn, wx);
  const int* idxp = g_idx + b*pn*pn;
  float val = 0.f;
  for (int ky=0; ky<pn; ky++){
    float wyv = wy[ky];
    for (int kx=0; kx<pn; kx++){
      float ww = wyv*wx[kx];
      if (ww != 0.f)
        val += ww * emb[(size_t)idxp[ky*pn+kx]*CC + c];
    }
  }
  g_h[((b*CC+c)*HH+y)*WW+x] = val;
}

__global__ void gather_kernel(const float* __restrict__ emb){
  int t = blockIdx.x*blockDim.x + threadIdx.x;
  if (t >= NELEM) return;
  int c = t & 127; int r = t >> 7;
  int x = r & 15; int y = (r>>4)&15; int b = r>>8;
  g_h[((b*CC+c)*HH+y)*WW+x] = emb[(size_t)g_idx[(b*16+y)*16+x]*CC + c];
}

// ---------------- Phi conv3x3 + blend + residual update + loss partial (f32x2) ----------------
// grid (8 co-groups, 32 batch), 128 threads; thread = 2 pixels x 16 c_out (8 co-pairs)
__global__ void __launch_bounds__(128) conv_phi_kernel(
    const float* __restrict__ f,
    const float* __restrict__ w,
    const float* __restrict__ bias,
    int si){
  __shared__ float in_s[8*18*18];
  __shared__ __align__(16) float w_s[8][9][16];
  __shared__ float red[128];
  int tid = threadIdx.x;
  int b = blockIdx.y, cog = blockIdx.x;
  int tx = tid & 15, ty = tid >> 4;   // ty 0..7

  ull acc0[8], acc1[8];
  #pragma unroll
  for (int i=0;i<8;i++){ acc0[i]=0ull; acc1[i]=0ull; }

  for (int cb=0; cb<16; cb++){
    __syncthreads();
    for (int idx=tid; idx<8*324; idx+=128){
      int q = idx/324; int r2 = idx - q*324;
      int iy = r2/18 - 1; int ix = r2 - (r2/18)*18 - 1;
      int ci = cb*8 + q;
      float v = 0.f;
      if (iy>=0 && iy<16 && ix>=0 && ix<16)
        v = g_h[((b*CC+ci)*HH+iy)*WW+ix];
      in_s[idx] = v;
    }
    for (int idx=tid; idx<1152; idx+=128){
      int q = idx/144; int r2 = idx - q*144;
      int t9 = r2 >> 4; int co = r2 & 15;
      w_s[q][t9][co] = w[((size_t)(cog*16+co)*CC + cb*8+q)*9 + t9];
    }
    __syncthreads();

    #pragma unroll
    for (int q=0;q<8;q++){
      float a[9], c2[9];
      const float* base = in_s + q*324;
      #pragma unroll
      for (int dy=0;dy<3;dy++)
        #pragma unroll
        for (int dx=0;dx<3;dx++){
          a[dy*3+dx]  = base[(ty+dy)*18 + tx+dx];
          c2[dy*3+dx] = base[(ty+8+dy)*18 + tx+dx];
        }
      #pragma unroll
      for (int t9=0;t9<9;t9++){
        ull av2 = pack2(a[t9],  a[t9]);
        ull bv2 = pack2(c2[t9], c2[t9]);
        const ulonglong2* wp = (const ulonglong2*)&w_s[q][t9][0];
        ulonglong2 w0 = wp[0], w1 = wp[1], w2 = wp[2], w3 = wp[3];
        acc0[0]=fma2(w0.x,av2,acc0[0]); acc0[1]=fma2(w0.y,av2,acc0[1]);
        acc0[2]=fma2(w1.x,av2,acc0[2]); acc0[3]=fma2(w1.y,av2,acc0[3]);
        acc0[4]=fma2(w2.x,av2,acc0[4]); acc0[5]=fma2(w2.y,av2,acc0[5]);
        acc0[6]=fma2(w3.x,av2,acc0[6]); acc0[7]=fma2(w3.y,av2,acc0[7]);
        acc1[0]=fma2(w0.x,bv2,acc1[0]); acc1[1]=fma2(w0.y,bv2,acc1[1]);
        acc1[2]=fma2(w1.x,bv2,acc1[2]); acc1[3]=fma2(w1.y,bv2,acc1[3]);
        acc1[4]=fma2(w2.x,bv2,acc1[4]); acc1[5]=fma2(w2.y,bv2,acc1[5]);
        acc1[6]=fma2(w3.x,bv2,acc1[6]); acc1[7]=fma2(w3.y,bv2,acc1[7]);
      }
    }
  }

  float lsum = 0.f;
  #pragma unroll
  for (int c2i=0; c2i<8; c2i++){
    float s0lo, s0hi, s1lo, s1hi;
    unpack2(acc0[c2i], s0lo, s0hi);
    unpack2(acc1[c2i], s1lo, s1hi);
    #pragma unroll
    for (int lane=0; lane<2; lane++){
      int co = cog*16 + c2i*2 + lane;
      float bs = bias[co];
      float sa = (lane==0)? s0lo : s0hi;
      float sb = (lane==0)? s1lo : s1hi;
      {
        int off = ((b*CC+co)*HH + ty)*WW + tx;
        float out = 0.5f*g_h[off] + 0.5f*(sa + bs);
        float fh = g_fhat[off] + out;
        g_fhat[off] = fh;
        g_rest[off] = g_rest[off] - out;
        float d = fh - f[off];
        lsum += d*d;
      }
      {
        int off = ((b*CC+co)*HH + ty+8)*WW + tx;
        float out = 0.5f*g_h[off] + 0.5f*(sb + bs);
        float fh = g_fhat[off] + out;
        g_fhat[off] = fh;
        g_rest[off] = g_rest[off] - out;
        float d = fh - f[off];
        lsum += d*d;
      }
    }
  }
  red[tid] = lsum;
  __syncthreads();
  for (int s=64; s>0; s>>=1){
    if (tid < s) red[tid] += red[tid+s];
    __syncthreads();
  }
  if (tid==0) g_loss[si*256 + b*8 + cog] = red[0];
}

// ---------------- output + loss (f_hat at [0..N), loss at [N]) ----------------
__global__ void output_kernel(const float* __restrict__ f, float* __restrict__ out, int out_size){
  int i = blockIdx.x*blockDim.x + threadIdx.x;
  if (out_size >= NELEM && i < NELEM)
    out[i] = (g_fhat[i] - f[i]) + f[i];   // straight-through rounding replicated
}

__global__ void loss_kernel(float* __restrict__ out, int out_size){
  __shared__ float m[SN];
  int tid = threadIdx.x;
  if (tid < SN){
    float s = 0.f;
    for (int i=0;i<256;i++) s += g_loss[tid*256+i];
    m[tid] = s * (1.f/(float)NELEM);
  }
  __syncthreads();
  if (tid == 0){
    float loss = 0.f;
    for (int si=0; si<SN; si++) loss += 0.25f*m[si] + m[si];
    loss *= (1.f/(float)SN);
    int pos = -1;
    if (out_size > NELEM) pos = NELEM;
    else if (out_size == 1) pos = 0;
    if (pos >= 0) out[pos] = loss;
  }
}

// ---------------- launch ----------------
extern "C" void kernel_launch(void* const* d_in, const int* in_sizes, int n_in,
                              void* d_out, int out_size){
  // positional inputs only (size-based remap is unsafe: NELEM == VV*CC)
  const float* f   = (const float*)d_in[0];
  const float* emb = (const float*)d_in[1];
  const float* pw  = (const float*)d_in[2];
  const float* pb  = (const float*)d_in[3];
  float* out = (float*)d_out;

  init_kernel<<<NELEM/256, 256>>>(f);
  esq_kernel<<<VV/256, 256>>>(emb);

  const int pns[SN]  = {1,2,4,8,16};
  const int chs[SN]  = {64,32,16,8,4};
  const int kphi[SN] = {0,1,2,2,3};   // exact IEEE-754 linspace argmin (R13-verified)

  for (int si=0; si<SN; si++){
    int pn = pns[si];
    int N = BB*pn*pn;
    pool_kernel<<<(N*CC+255)/256, 256>>>(pn, N);
    dim3 ga(N/32, chs[si]);
    argmin_stageA<<<ga, 128>>>(emb, chs[si]);
    argmin_stageB<<<(N+255)/256, 256>>>(N, chs[si]);
    if (si < SN-1) upsample_kernel<<<NELEM/256, 256>>>(emb, pn);
    else           gather_kernel<<<NELEM/256, 256>>>(emb);
    conv_phi_kernel<<<dim3(8,32), 128>>>(f, pw + (size_t)kphi[si]*CC*CC*9, pb + kphi[si]*CC, si);
  }

  output_kernel<<<NELEM/256, 256>>>(f, out, out_size);
  loss_kernel<<<1, 32>>>(out, out_size);
}

// round 16
// speedup vs baseline: 1.1786x; 1.1289x over previous
#include <cuda_runtime.h>

#define CC 128
#define HH 16
#define WW 16
#define BB 32
#define VV 8192
#define NELEM (BB*CC*HH*WW)   // 1048576 elements (== VV*CC — never size-remap!)
#define SN 5

typedef unsigned long long ull;

__device__ __forceinline__ ull pack2(float lo, float hi){
  ull r; asm("mov.b64 %0, {%1, %2};" : "=l"(r) : "f"(lo), "f"(hi)); return r;
}
__device__ __forceinline__ void unpack2(ull v, float& lo, float& hi){
  asm("mov.b64 {%0, %1}, %2;" : "=f"(lo), "=f"(hi) : "l"(v));
}
// packed dual fp32 FMA (Blackwell FFMA2; lanes independent => bit-exact per-lane fp32)
__device__ __forceinline__ ull fma2(ull a, ull b, ull c){
  ull r; asm("fma.rn.f32x2 %0, %1, %2, %3;" : "=l"(r) : "l"(a), "l"(b), "l"(c)); return r;
}

// ---------------- device scratch (no allocations allowed) ----------------
__device__ float g_rest[NELEM];
__device__ float g_fhat[NELEM];
__device__ float g_x[VV*CC];        // pooled vectors, [n][c], n-major
__device__ float g_esq[VV];
__device__ float g_pd[32768];       // partial min dist per (n, chunk)
__device__ int   g_pi[32768];
__device__ int   g_idx[VV];
__device__ float g_h[NELEM];        // current-scale h (upsampled, pre-phi)
__device__ float g_loss[SN*256];    // per-scale per-conv-block loss partials

// ---------------- init ----------------
__global__ void init_kernel(const float* __restrict__ f){
  int i = blockIdx.x*blockDim.x + threadIdx.x;
  if (i < NELEM){ g_rest[i]=f[i]; g_fhat[i]=0.f; }
}

__global__ void esq_kernel(const float* __restrict__ emb){
  int v = blockIdx.x*blockDim.x + threadIdx.x;
  if (v >= VV) return;
  const float4* r = (const float4*)(emb + (size_t)v*CC);
  float s=0.f;
  #pragma unroll
  for (int q=0;q<CC/4;q++){ float4 e=r[q]; s += e.x*e.x+e.y*e.y+e.z*e.z+e.w*e.w; }
  g_esq[v]=s;
}

// ---------------- avg pool (area interpolate) ----------------
__global__ void pool_kernel(int pn, int N){
  int t = blockIdx.x*blockDim.x + threadIdx.x;
  if (t >= N*CC) return;
  int c = t & (CC-1); int n = t >> 7;
  int pp = pn*pn; int b = n/pp; int r = n - b*pp; int y = r/pn; int x = r - y*pn;
  int s = HH/pn;
  const float* base = g_rest + ((b*CC + c)*HH + y*s)*WW + x*s;
  float sum = 0.f;
  for (int dy=0; dy<s; dy++)
    for (int dx=0; dx<s; dx++)
      sum += base[dy*WW + dx];
  g_x[(size_t)n*CC + c] = sum * (1.f/(float)(s*s));
}

// ---------------- argmin stage A v2: 64n x 64v tiles, 4n x 8v per thread ----------------
// smem (dynamic 64KB): xs[128k][64n] | es[128k][64v]
// Per-(n,v) distance = e_sq[v] - 2*sum_k x_k e_k, single ascending-k fma chain
// (bit-identical to R13/R15). 1.5 B/MAC from smem -> FFMA2-pipe-bound.
__global__ void __launch_bounds__(128) argmin_stageA(const float* __restrict__ emb,
                                                     int nch, int Nvalid){
  extern __shared__ __align__(16) float dsm[];
  float (*xs)[64] = (float (*)[64])dsm;            // 32KB
  float (*es)[64] = (float (*)[64])(dsm + 128*64); // 32KB
  int tid = threadIdx.x;
  int n0 = blockIdx.x * 64;
  int L = VV / nch;
  int vbeg = blockIdx.y * L;

  // fill xs: 64 rows (n), 128 k each; thread = half-row
  {
    int i = tid >> 1, half = (tid & 1)*64;
    const float4* src = (const float4*)(g_x + (size_t)(n0+i)*CC + half);
    #pragma unroll
    for (int q=0;q<16;q++){
      float4 x4 = src[q];
      int k = half + q*4;
      xs[k  ][i]=x4.x; xs[k+1][i]=x4.y; xs[k+2][i]=x4.z; xs[k+3][i]=x4.w;
    }
  }

  float bd[4]; int bi[4];
  #pragma unroll
  for (int i=0;i<4;i++){ bd[i]=3.4e38f; bi[i]=0; }
  int tn = tid & 15, tv = tid >> 4;   // 16 n-groups (4n) x 8 v-groups (8v)
  int nb = tn*4, vb = tv*8;

  for (int sub=0; sub<L; sub+=64){
    int v0 = vbeg + sub;
    __syncthreads();
    {
      int vr = tid >> 1, half = (tid & 1)*64;
      const float4* src = (const float4*)(emb + (size_t)(v0+vr)*CC + half);
      #pragma unroll
      for (int q=0;q<16;q++){
        float4 e4 = src[q];
        int k = half + q*4;
        es[k  ][vr]=e4.x; es[k+1][vr]=e4.y; es[k+2][vr]=e4.z; es[k+3][vr]=e4.w;
      }
    }
    __syncthreads();

    ull acc[4][4];   // [n][vpair]
    #pragma unroll
    for (int i=0;i<4;i++)
      #pragma unroll
      for (int j=0;j<4;j++) acc[i][j]=0ull;

    #pragma unroll 4
    for (int k=0;k<128;k++){
      float4 xv = *(const float4*)&xs[k][nb];
      ull x0 = pack2(xv.x, xv.x);
      ull x1 = pack2(xv.y, xv.y);
      ull x2 = pack2(xv.z, xv.z);
      ull x3 = pack2(xv.w, xv.w);
      const ulonglong2* ep = (const ulonglong2*)&es[k][vb];
      ulonglong2 ea = ep[0];
      ulonglong2 eb = ep[1];
      acc[0][0]=fma2(x0,ea.x,acc[0][0]); acc[0][1]=fma2(x0,ea.y,acc[0][1]);
      acc[0][2]=fma2(x0,eb.x,acc[0][2]); acc[0][3]=fma2(x0,eb.y,acc[0][3]);
      acc[1][0]=fma2(x1,ea.x,acc[1][0]); acc[1][1]=fma2(x1,ea.y,acc[1][1]);
      acc[1][2]=fma2(x1,eb.x,acc[1][2]); acc[1][3]=fma2(x1,eb.y,acc[1][3]);
      acc[2][0]=fma2(x2,ea.x,acc[2][0]); acc[2][1]=fma2(x2,ea.y,acc[2][1]);
      acc[2][2]=fma2(x2,eb.x,acc[2][2]); acc[2][3]=fma2(x2,eb.y,acc[2][3]);
      acc[3][0]=fma2(x3,ea.x,acc[3][0]); acc[3][1]=fma2(x3,ea.y,acc[3][1]);
      acc[3][2]=fma2(x3,eb.x,acc[3][2]); acc[3][3]=fma2(x3,eb.y,acc[3][3]);
    }

    // epilogue: per n, v ascending (pairs then lanes), strict < => first-min
    #pragma unroll
    for (int j2=0;j2<4;j2++){
      int v = v0 + vb + j2*2;
      float eqlo = g_esq[v], eqhi = g_esq[v+1];
      #pragma unroll
      for (int i=0;i<4;i++){
        float alo, ahi; unpack2(acc[i][j2], alo, ahi);
        float dlo = eqlo - 2.f*alo;
        if (dlo < bd[i]){ bd[i]=dlo; bi[i]=v; }
        float dhi = eqhi - 2.f*ahi;
        if (dhi < bd[i]){ bd[i]=dhi; bi[i]=v+1; }
      }
    }
  }

  // block reduce: per n, 8 v-group candidates (reuse es region as scratch)
  __syncthreads();
  float* rd = &es[0][0];           // 512 floats
  int*   ri = (int*)&es[16][0];    // 512 ints (disjoint rows)
  #pragma unroll
  for (int i=0;i<4;i++){
    rd[(nb+i)*8 + tv] = bd[i];
    ri[(nb+i)*8 + tv] = bi[i];
  }
  __syncthreads();
  if (tid < 64 && n0 + tid < Nvalid){
    float best = 3.4e38f; int besti = 0x7fffffff;
    #pragma unroll
    for (int t=0;t<8;t++){
      float d = rd[tid*8 + t]; int ii = ri[tid*8 + t];
      if (d < best || (d == best && ii < besti)){ best = d; besti = ii; }
    }
    g_pd[(size_t)(n0+tid)*nch + blockIdx.y] = best;
    g_pi[(size_t)(n0+tid)*nch + blockIdx.y] = besti;
  }
}

__global__ void argmin_stageB(int N, int nch){
  int n = blockIdx.x*blockDim.x + threadIdx.x;
  if (n >= N) return;
  float bd = g_pd[(size_t)n*nch]; int bi = g_pi[(size_t)n*nch];
  for (int c=1;c<nch;c++){
    float d = g_pd[(size_t)n*nch + c]; int ii = g_pi[(size_t)n*nch + c];
    if (d < bd || (d == bd && ii < bi)){ bd = d; bi = ii; }
  }
  g_idx[n] = bi;
}

// ---------------- bicubic upsample (jax cubic: Keys a=-0.5 + tap-sum norm) ----
__device__ __forceinline__ float keysf(float x){
  x = fabsf(x);
  if (x < 1.f) return ((1.5f*x - 2.5f)*x)*x + 1.f;
  if (x < 2.f) return ((-0.5f*x + 2.5f)*x - 4.f)*x + 2.f;
  return 0.f;
}
__device__ __forceinline__ void mkw(int i, int pn, float* w){
  float sf = (i + 0.5f)*((float)pn*(1.f/16.f)) - 0.5f;
  float s = 0.f;
  for (int k=0;k<pn;k++){ float wv = keysf(sf - (float)k); w[k]=wv; s+=wv; }
  float inv = 1.f/s;
  for (int k=0;k<pn;k++) w[k]*=inv;
}

__global__ void upsample_kernel(const float* __restrict__ emb, int pn){
  int t = blockIdx.x*blockDim.x + threadIdx.x;
  if (t >= NELEM) return;
  int c = t & 127; int r = t >> 7;
  int x = r & 15; int y = (r>>4)&15; int b = r>>8;
  float wy[8], wx[8];
  mkw(y, pn, wy); mkw(x, pn, wx);
  const int* idxp = g_idx + b*pn*pn;
  float val = 0.f;
  for (int ky=0; ky<pn; ky++){
    float wyv = wy[ky];
    for (int kx=0; kx<pn; kx++){
      float ww = wyv*wx[kx];
      if (ww != 0.f)
        val += ww * emb[(size_t)idxp[ky*pn+kx]*CC + c];
    }
  }
  g_h[((b*CC+c)*HH+y)*WW+x] = val;
}

__global__ void gather_kernel(const float* __restrict__ emb){
  int t = blockIdx.x*blockDim.x + threadIdx.x;
  if (t >= NELEM) return;
  int c = t & 127; int r = t >> 7;
  int x = r & 15; int y = (r>>4)&15; int b = r>>8;
  g_h[((b*CC+c)*HH+y)*WW+x] = emb[(size_t)g_idx[(b*16+y)*16+x]*CC + c];
}

// ---------------- Phi conv3x3 + blend + residual update + loss partial (f32x2) ----------------
__global__ void __launch_bounds__(128) conv_phi_kernel(
    const float* __restrict__ f,
    const float* __restrict__ w,
    const float* __restrict__ bias,
    int si){
  __shared__ float in_s[8*18*18];
  __shared__ __align__(16) float w_s[8][9][16];
  __shared__ float red[128];
  int tid = threadIdx.x;
  int b = blockIdx.y, cog = blockIdx.x;
  int tx = tid & 15, ty = tid >> 4;   // ty 0..7

  ull acc0[8], acc1[8];
  #pragma unroll
  for (int i=0;i<8;i++){ acc0[i]=0ull; acc1[i]=0ull; }

  for (int cb=0; cb<16; cb++){
    __syncthreads();
    for (int idx=tid; idx<8*324; idx+=128){
      int q = idx/324; int r2 = idx - q*324;
      int iy = r2/18 - 1; int ix = r2 - (r2/18)*18 - 1;
      int ci = cb*8 + q;
      float v = 0.f;
      if (iy>=0 && iy<16 && ix>=0 && ix<16)
        v = g_h[((b*CC+ci)*HH+iy)*WW+ix];
      in_s[idx] = v;
    }
    for (int idx=tid; idx<1152; idx+=128){
      int q = idx/144; int r2 = idx - q*144;
      int t9 = r2 >> 4; int co = r2 & 15;
      w_s[q][t9][co] = w[((size_t)(cog*16+co)*CC + cb*8+q)*9 + t9];
    }
    __syncthreads();

    #pragma unroll
    for (int q=0;q<8;q++){
      float a[9], c2[9];
      const float* base = in_s + q*324;
      #pragma unroll
      for (int dy=0;dy<3;dy++)
        #pragma unroll
        for (int dx=0;dx<3;dx++){
          a[dy*3+dx]  = base[(ty+dy)*18 + tx+dx];
          c2[dy*3+dx] = base[(ty+8+dy)*18 + tx+dx];
        }
      #pragma unroll
      for (int t9=0;t9<9;t9++){
        ull av2 = pack2(a[t9],  a[t9]);
        ull bv2 = pack2(c2[t9], c2[t9]);
        const ulonglong2* wp = (const ulonglong2*)&w_s[q][t9][0];
        ulonglong2 w0 = wp[0], w1 = wp[1], w2 = wp[2], w3 = wp[3];
        acc0[0]=fma2(w0.x,av2,acc0[0]); acc0[1]=fma2(w0.y,av2,acc0[1]);
        acc0[2]=fma2(w1.x,av2,acc0[2]); acc0[3]=fma2(w1.y,av2,acc0[3]);
        acc0[4]=fma2(w2.x,av2,acc0[4]); acc0[5]=fma2(w2.y,av2,acc0[5]);
        acc0[6]=fma2(w3.x,av2,acc0[6]); acc0[7]=fma2(w3.y,av2,acc0[7]);
        acc1[0]=fma2(w0.x,bv2,acc1[0]); acc1[1]=fma2(w0.y,bv2,acc1[1]);
        acc1[2]=fma2(w1.x,bv2,acc1[2]); acc1[3]=fma2(w1.y,bv2,acc1[3]);
        acc1[4]=fma2(w2.x,bv2,acc1[4]); acc1[5]=fma2(w2.y,bv2,acc1[5]);
        acc1[6]=fma2(w3.x,bv2,acc1[6]); acc1[7]=fma2(w3.y,bv2,acc1[7]);
      }
    }
  }

  float lsum = 0.f;
  #pragma unroll
  for (int c2i=0; c2i<8; c2i++){
    float s0lo, s0hi, s1lo, s1hi;
    unpack2(acc0[c2i], s0lo, s0hi);
    unpack2(acc1[c2i], s1lo, s1hi);
    #pragma unroll
    for (int lane=0; lane<2; lane++){
      int co = cog*16 + c2i*2 + lane;
      float bs = bias[co];
      float sa = (lane==0)? s0lo : s0hi;
      float sb = (lane==0)? s1lo : s1hi;
      {
        int off = ((b*CC+co)*HH + ty)*WW + tx;
        float out = 0.5f*g_h[off] + 0.5f*(sa + bs);
        float fh = g_fhat[off] + out;
        g_fhat[off] = fh;
        g_rest[off] = g_rest[off] - out;
        float d = fh - f[off];
        lsum += d*d;
      }
      {
        int off = ((b*CC+co)*HH + ty+8)*WW + tx;
        float out = 0.5f*g_h[off] + 0.5f*(sb + bs);
        float fh = g_fhat[off] + out;
        g_fhat[off] = fh;
        g_rest[off] = g_rest[off] - out;
        float d = fh - f[off];
        lsum += d*d;
      }
    }
  }
  red[tid] = lsum;
  __syncthreads();
  for (int s=64; s>0; s>>=1){
    if (tid < s) red[tid] += red[tid+s];
    __syncthreads();
  }
  if (tid==0) g_loss[si*256 + b*8 + cog] = red[0];
}

// ---------------- output + loss (f_hat at [0..N), loss at [N]) ----------------
__global__ void output_kernel(const float* __restrict__ f, float* __restrict__ out, int out_size){
  int i = blockIdx.x*blockDim.x + threadIdx.x;
  if (out_size >= NELEM && i < NELEM)
    out[i] = (g_fhat[i] - f[i]) + f[i];   // straight-through rounding replicated
}

__global__ void loss_kernel(float* __restrict__ out, int out_size){
  __shared__ float m[SN];
  int tid = threadIdx.x;
  if (tid < SN){
    float s = 0.f;
    for (int i=0;i<256;i++) s += g_loss[tid*256+i];
    m[tid] = s * (1.f/(float)NELEM);
  }
  __syncthreads();
  if (tid == 0){
    float loss = 0.f;
    for (int si=0; si<SN; si++) loss += 0.25f*m[si] + m[si];
    loss *= (1.f/(float)SN);
    int pos = -1;
    if (out_size > NELEM) pos = NELEM;
    else if (out_size == 1) pos = 0;
    if (pos >= 0) out[pos] = loss;
  }
}

// ---------------- launch ----------------
extern "C" void kernel_launch(void* const* d_in, const int* in_sizes, int n_in,
                              void* d_out, int out_size){
  // positional inputs only (size-based remap is unsafe: NELEM == VV*CC)
  const float* f   = (const float*)d_in[0];
  const float* emb = (const float*)d_in[1];
  const float* pw  = (const float*)d_in[2];
  const float* pb  = (const float*)d_in[3];
  float* out = (float*)d_out;

  // opt-in to 64KB dynamic smem for stageA (host API, idempotent, capture-legal)
  static int smem_set = 0;
  if (!smem_set){
    cudaFuncSetAttribute(argmin_stageA, cudaFuncAttributeMaxDynamicSharedMemorySize, 65536);
    smem_set = 1;
  }

  init_kernel<<<NELEM/256, 256>>>(f);
  esq_kernel<<<VV/256, 256>>>(emb);

  const int pns[SN]  = {1,2,4,8,16};
  const int chs[SN]  = {128,64,16,8,4};  // v-chunks: keep >=128 blocks in flight
  const int kphi[SN] = {0,1,2,2,3};      // exact IEEE-754 linspace argmin (R13-verified)

  for (int si=0; si<SN; si++){
    int pn = pns[si];
    int N = BB*pn*pn;
    pool_kernel<<<(N*CC+255)/256, 256>>>(pn, N);
    dim3 ga((N+63)/64, chs[si]);
    argmin_stageA<<<ga, 128, 65536>>>(emb, chs[si], N);
    argmin_stageB<<<(N+255)/256, 256>>>(N, chs[si]);
    if (si < SN-1) upsample_kernel<<<NELEM/256, 256>>>(emb, pn);
    else           gather_kernel<<<NELEM/256, 256>>>(emb);
    conv_phi_kernel<<<dim3(8,32), 128>>>(f, pw + (size_t)kphi[si]*CC*CC*9, pb + kphi[si]*CC, si);
  }

  output_kernel<<<NELEM/256, 256>>>(f, out, out_size);
  loss_kernel<<<1, 32>>>(out, out_size);
}